// round 13
// baseline (speedup 1.0000x reference)
#include <cuda_runtime.h>
#include <cuda_fp16.h>
#include <mma.h>
#include <cstdint>

using namespace nvcuda;

#define D_INc   4096
#define D_OUTc  4096
#define NEXP    8
#define RANKD   16
#define ERD     128          // NEXP * RANKD
#define SCALINGF 2.0f
#define T_MAXc  8192
#define KSPLIT  4

// scratch: fp16 operand copies + fp32 split-K partials
__device__ __half g_xh [T_MAXc * D_INc];          // 64MB
__device__ __half g_Wbh[D_OUTc * D_INc];          // 32MB
__device__ __half g_Ah [ERD * D_INc];             // 1MB
__device__ __half g_Bfh[D_OUTc * ERD];            // 1MB  repacked B_flat
__device__ __half g_hh [T_MAXc * ERD];            // 2MB  weighted h'
__device__ float  g_hp [KSPLIT * T_MAXc * ERD];   // 16MB h partials

// ---------------------------------------------------------------------------
// cp.async helpers
// ---------------------------------------------------------------------------
__device__ __forceinline__ void cpa16(uint32_t dst, const void* src) {
    asm volatile("cp.async.cg.shared.global [%0], [%1], 16;" :: "r"(dst), "l"(src));
}
#define CP_COMMIT() asm volatile("cp.async.commit_group;")
#define CP_WAIT1()  asm volatile("cp.async.wait_group 1;")

// ---------------------------------------------------------------------------
// Fused tiled WMMA FP16 GEMM (fp32 accum), 3-stage cp.async pipeline.
//   Block tile 256(M) x 128(N), BK=64 halves, 512 threads, 16 warps (4M x 4N),
//   warp tile 64x32 (rd10-proven shape), 1 CTA/SM = 16 warps/SM, regs<=128.
//   C[M,N](fp32) = concat-K GEMM + bias:
//     chunks 0..nc1-1       : A = pA1 (ldA1), B = pB1 (ldB1), K off kbase+c*64
//     chunks nc1..nc1+nc2-1 : A = pA2 (ldA2), B = pB2 (ldB2)
//   ksplit != 0: blockIdx.x = K-slice (n0=0, out += slice*sliceStride,
//                kbase = slice*nc1*64)
// ---------------------------------------------------------------------------
#define BM      256
#define BKH     64                    // halves per K chunk
#define LDTH    72                    // smem row stride (halves), +8 pad
#define A_H     (BM  * LDTH)          // halves in A tile
#define B_H     (128 * LDTH)          // halves in B tile
#define STAGE_B ((A_H + B_H) * 2)     // 55296 B per stage
#define NSTG    3
#define LDE     132                   // epilogue smem stride (floats)

__global__ __launch_bounds__(512, 1)
void fused_gemm(const __half* __restrict__ pA1, int ldA1,
                const __half* __restrict__ pB1, int ldB1,
                const __half* __restrict__ pA2, int ldA2,
                const __half* __restrict__ pB2, int ldB2,
                int nc1, int nc2,
                const float* __restrict__ bias,
                float* __restrict__ out, int ldC,
                int ksplit, int sliceStride)
{
    extern __shared__ __align__(16) char smem[];
    float* sb = (float*)smem;                      // bias tile [128]
    char*  stage_base = smem + 1024;
    const uint32_t stage_s = (uint32_t)__cvta_generic_to_shared(stage_base);

    const int tid  = threadIdx.x;
    const int warpId = tid >> 5;
    const int wm = warpId & 3;    // 0..3 (M dir, 64 rows each)
    const int wn = warpId >> 2;   // 0..3 (N dir, 32 cols each)
    const int m0 = blockIdx.y * BM;
    const int NC = nc1 + nc2;

    int n0, kbase;
    float* outp = out;
    if (ksplit) {
        n0 = 0;
        kbase = blockIdx.x * nc1 * BKH;
        outp  = out + (size_t)blockIdx.x * sliceStride;
    } else {
        n0 = blockIdx.x * 128;
        kbase = 0;
    }

    for (int i = tid; i < 128; i += 512)
        sb[i] = bias ? bias[n0 + i] : 0.0f;

    wmma::fragment<wmma::accumulator, 16, 16, 16, float> acc[4][2];
#pragma unroll
    for (int i = 0; i < 4; i++)
#pragma unroll
        for (int j = 0; j < 2; j++)
            wmma::fill_fragment(acc[i][j], 0.0f);

    // ---- async load of one K-chunk (A[256x64h] + B[128x64h]) into stage st ----
    auto load_chunk = [&](int c, int st) {
        const __half* bA; int lda; const __half* bB; int ldb; int kof;
        if (c < nc1) { bA = pA1; lda = ldA1; bB = pB1; ldb = ldB1; kof = kbase + c * BKH; }
        else         { bA = pA2; lda = ldA2; bB = pB2; ldb = ldB2; kof = (c - nc1) * BKH; }
        uint32_t sA = stage_s + st * STAGE_B;
        uint32_t sB = sA + A_H * 2;
#pragma unroll
        for (int it = 0; it < 4; it++) {           // A: 256 rows x 8 segs(16B)
            int idx = tid + it * 512;
            int row = idx >> 3;
            int sg  = idx & 7;
            cpa16(sA + (uint32_t)(row * LDTH + sg * 8) * 2,
                  bA + (size_t)(m0 + row) * lda + kof + sg * 8);
        }
#pragma unroll
        for (int it = 0; it < 2; it++) {           // B: 128 rows x 8 segs
            int idx = tid + it * 512;
            int row = idx >> 3;
            int sg  = idx & 7;
            cpa16(sB + (uint32_t)(row * LDTH + sg * 8) * 2,
                  bB + (size_t)(n0 + row) * ldb + kof + sg * 8);
        }
        CP_COMMIT();
    };

    // prologue: 2 chunks in flight
    load_chunk(0, 0);
    load_chunk(1, 1);

    int st_c = 0, st_l = 2;
    for (int c = 0; c < NC; c++) {
        CP_WAIT1();
        __syncthreads();
        if (c + 2 < NC) {
            load_chunk(c + 2, st_l);
            if (++st_l == NSTG) st_l = 0;
        }

        const __half* As = (const __half*)(stage_base + st_c * STAGE_B);
        const __half* Bs = As + A_H;
        if (++st_c == NSTG) st_c = 0;

#pragma unroll
        for (int kk = 0; kk < BKH; kk += 16) {
            wmma::fragment<wmma::matrix_a, 16, 16, 16, __half, wmma::row_major> af[4];
            wmma::fragment<wmma::matrix_b, 16, 16, 16, __half, wmma::col_major> bf[2];
#pragma unroll
            for (int i = 0; i < 4; i++)
                wmma::load_matrix_sync(af[i], &As[(wm * 64 + i * 16) * LDTH + kk], LDTH);
#pragma unroll
            for (int j = 0; j < 2; j++)
                wmma::load_matrix_sync(bf[j], &Bs[(wn * 32 + j * 16) * LDTH + kk], LDTH);
#pragma unroll
            for (int i = 0; i < 4; i++)
#pragma unroll
                for (int j = 0; j < 2; j++)
                    wmma::mma_sync(acc[i][j], af[i], bf[j], acc[i][j]);
        }
    }

    // ---- epilogue: frags -> smem(fp32) -> +bias -> coalesced float4 stores ----
    __syncthreads();
    float* sE = (float*)stage_base;    // 256 x LDE floats = 135KB, fits stages
#pragma unroll
    for (int i = 0; i < 4; i++)
#pragma unroll
        for (int j = 0; j < 2; j++)
            wmma::store_matrix_sync(&sE[(wm * 64 + i * 16) * LDE + wn * 32 + j * 16],
                                    acc[i][j], LDE, wmma::mem_row_major);
    __syncthreads();

#pragma unroll
    for (int it = 0; it < 16; it++) {
        int i4  = tid + it * 512;     // 0..8191 float4s (256 rows x 32)
        int row = i4 >> 5;
        int c4  = i4 & 31;
        float4 v = *(const float4*)&sE[row * LDE + c4 * 4];
        v.x += sb[c4 * 4 + 0];
        v.y += sb[c4 * 4 + 1];
        v.z += sb[c4 * 4 + 2];
        v.w += sb[c4 * 4 + 3];
        *(float4*)(outp + (size_t)(m0 + row) * ldC + n0 + c4 * 4) = v;
    }
}

// ---------------------------------------------------------------------------
// fp32 -> fp16 convert copy: 8 elems/thread
// ---------------------------------------------------------------------------
__global__ __launch_bounds__(256)
void to_half_kernel(const float* __restrict__ src, __half* __restrict__ dst, int n8)
{
    int i = blockIdx.x * 256 + threadIdx.x;
    if (i < n8) {
        const float4* s = (const float4*)(src + (size_t)i * 8);
        float4 a = s[0], b = s[1];
        __half2 h[4];
        h[0] = __floats2half2_rn(a.x, a.y);
        h[1] = __floats2half2_rn(a.z, a.w);
        h[2] = __floats2half2_rn(b.x, b.y);
        h[3] = __floats2half2_rn(b.z, b.w);
        *(uint4*)(dst + (size_t)i * 8) = *(uint4*)h;
    }
}

// ---------------------------------------------------------------------------
// Repack + convert B: Bfh[n][e*16+r] = fp16(Bw[e][n][r])
// ---------------------------------------------------------------------------
__global__ __launch_bounds__(256)
void repack_B_kernel(const float* __restrict__ Bw, __half* __restrict__ Bfh)
{
    int idx = blockIdx.x * 256 + threadIdx.x;   // over 4096 * 32 groups of 4
    int n  = idx >> 5;
    int j4 = idx & 31;
    int j  = j4 * 4;
    int e  = j >> 4;
    int r  = j & 15;
    float4 v = *(const float4*)(Bw + (size_t)e * (D_OUTc * RANKD) + (size_t)n * RANKD + r);
    __half2 h[2];
    h[0] = __floats2half2_rn(v.x, v.y);
    h[1] = __floats2half2_rn(v.z, v.w);
    *(uint2*)(Bfh + (size_t)n * ERD + j) = *(uint2*)h;
}

// ---------------------------------------------------------------------------
// Router: logits = x @ Wr^T (fp32), top-2 softmax;
// h'fp16 = fp16(sum_s hp[s] * wv[e] * SCALING)
// ---------------------------------------------------------------------------
__global__ __launch_bounds__(256)
void router_kernel(const float* __restrict__ x,
                   const float* __restrict__ Wr,
                   const float* __restrict__ hp,   // [KSPLIT][T][128]
                   __half* __restrict__ h,
                   int T)
{
    const int t = blockIdx.x;
    const float* xr = x + (size_t)t * D_INc;

    float acc[NEXP];
#pragma unroll
    for (int e = 0; e < NEXP; e++) acc[e] = 0.0f;
    for (int j = threadIdx.x; j < D_INc; j += 256) {
        float xv = xr[j];
#pragma unroll
        for (int e = 0; e < NEXP; e++) acc[e] += xv * Wr[e * D_INc + j];
    }
#pragma unroll
    for (int off = 16; off > 0; off >>= 1)
#pragma unroll
        for (int e = 0; e < NEXP; e++) acc[e] += __shfl_xor_sync(0xffffffffu, acc[e], off);

    __shared__ float sred[8][NEXP];
    const int warp = threadIdx.x >> 5;
    const int lane = threadIdx.x & 31;
    if (lane == 0)
#pragma unroll
        for (int e = 0; e < NEXP; e++) sred[warp][e] = acc[e];
    __syncthreads();

    __shared__ float wv[NEXP];
    if (threadIdx.x == 0) {
        float l[NEXP];
#pragma unroll
        for (int e = 0; e < NEXP; e++) {
            float s = 0.0f;
#pragma unroll
            for (int w = 0; w < 8; w++) s += sred[w][e];
            l[e] = s;
        }
        int i0 = 0;
#pragma unroll
        for (int e = 1; e < NEXP; e++) if (l[e] > l[i0]) i0 = e;
        int i1 = -1;
#pragma unroll
        for (int e = 0; e < NEXP; e++) {
            if (e == i0) continue;
            if (i1 < 0 || l[e] > l[i1]) i1 = e;
        }
        float m  = l[i0];
        float e0 = expf(l[i0] - m);
        float e1 = expf(l[i1] - m);
        float s  = e0 + e1;
#pragma unroll
        for (int e = 0; e < NEXP; e++) wv[e] = 0.0f;
        wv[i0] = e0 / s;
        wv[i1] = e1 / s;
    }
    __syncthreads();

    if (threadIdx.x < ERD) {
        int e = threadIdx.x >> 4;
        size_t base = (size_t)t * ERD + threadIdx.x;
        size_t ss = (size_t)T * ERD;
        float v = hp[base] + hp[base + ss] + hp[base + 2 * ss] + hp[base + 3 * ss];
        h[base] = __float2half_rn(v * (wv[e] * SCALINGF));
    }
}

// ---------------------------------------------------------------------------
extern "C" void kernel_launch(void* const* d_in, const int* in_sizes, int n_in,
                              void* d_out, int out_size)
{
    const float* x  = (const float*)d_in[0];   // [T, 4096]
    const float* Wb = (const float*)d_in[1];   // [4096, 4096]
    const float* bb = (const float*)d_in[2];   // [4096]
    const float* Wr = (const float*)d_in[3];   // [8, 4096]
    const float* Aw = (const float*)d_in[4];   // [8,16,4096] == [128,4096]
    const float* Bw = (const float*)d_in[5];   // [8,4096,16]
    float* out = (float*)d_out;

    const int T = in_sizes[0] / D_INc;         // 8192

    __half *xh, *wbh, *ah, *bfh, *hh;
    float  *hp;
    cudaGetSymbolAddress((void**)&xh,  g_xh);
    cudaGetSymbolAddress((void**)&wbh, g_Wbh);
    cudaGetSymbolAddress((void**)&ah,  g_Ah);
    cudaGetSymbolAddress((void**)&bfh, g_Bfh);
    cudaGetSymbolAddress((void**)&hh,  g_hh);
    cudaGetSymbolAddress((void**)&hp,  g_hp);

    constexpr int SMEM = 1024 + NSTG * STAGE_B;   // 166,912 B

    static bool attr_done = false;
    if (!attr_done) {
        cudaFuncSetAttribute(fused_gemm, cudaFuncAttributeMaxDynamicSharedMemorySize, SMEM);
        attr_done = true;
    }

    // --- prepass: fp16 conversions ---
    {
        int n8x = T * D_INc / 8;
        to_half_kernel<<<(n8x + 255) / 256, 256>>>(x, xh, n8x);
        int n8w = D_OUTc * D_INc / 8;
        to_half_kernel<<<(n8w + 255) / 256, 256>>>(Wb, wbh, n8w);
        int n8a = ERD * D_INc / 8;
        to_half_kernel<<<(n8a + 255) / 256, 256>>>(Aw, ah, n8a);
        repack_B_kernel<<<(D_OUTc * 32) / 256, 256>>>(Bw, bfh);
    }

    // --- h partials = x @ A^T, split-K across 4 slices (grid 4 x 32) ---
    fused_gemm<<<dim3(KSPLIT, T / BM), 512, SMEM>>>(
        xh, D_INc, ah, D_INc,
        xh, D_INc, ah, D_INc,
        D_INc / BKH / KSPLIT, 0, nullptr, hp, ERD,
        1, T * ERD);

    // --- router: top-2 softmax weights, reduce partials, scale h' -> fp16 ---
    router_kernel<<<T, 256>>>(x, Wr, hp, hh, T);

    // --- out = [x | h'] @ [Wb | Bf]^T + bias ---
    fused_gemm<<<dim3(D_OUTc / 128, T / BM), 512, SMEM>>>(
        xh, D_INc, wbh, D_INc,
        hh, ERD, bfh, ERD,
        D_INc / BKH, ERD / BKH, bb, out, D_OUTc,
        0, 0);
}

// round 14
// speedup vs baseline: 1.0317x; 1.0317x over previous
#include <cuda_runtime.h>
#include <cuda_fp16.h>
#include <mma.h>
#include <cstdint>

using namespace nvcuda;

#define D_INc   4096
#define D_OUTc  4096
#define NEXP    8
#define RANKD   16
#define ERD     128          // NEXP * RANKD
#define SCALINGF 2.0f
#define T_MAXc  8192
#define KSPLIT  4

// scratch: fp16 operand copies + fp32 split-K partials
__device__ __half g_xh [T_MAXc * D_INc];          // 64MB
__device__ __half g_Wbh[D_OUTc * D_INc];          // 32MB
__device__ __half g_Ah [ERD * D_INc];             // 1MB
__device__ __half g_Bfh[D_OUTc * ERD];            // 1MB  repacked B_flat
__device__ __half g_hh [T_MAXc * ERD];            // 2MB  weighted h'
__device__ float  g_hp [KSPLIT * T_MAXc * ERD];   // 16MB h partials

// ---------------------------------------------------------------------------
// cp.async helpers
// ---------------------------------------------------------------------------
__device__ __forceinline__ void cpa16(uint32_t dst, const void* src) {
    asm volatile("cp.async.cg.shared.global [%0], [%1], 16;" :: "r"(dst), "l"(src));
}
#define CP_COMMIT() asm volatile("cp.async.commit_group;")
#define CP_WAIT1()  asm volatile("cp.async.wait_group 1;")

// ---------------------------------------------------------------------------
// Fused tiled WMMA FP16 GEMM (fp32 accum), 3-stage cp.async pipeline.
//   Block tile 128x128, BK=64 halves, **128 threads / 4 warps (2M x 2N)**,
//   warp tile 64x64 (acc[4][4]); 2 CTAs/SM (smem 111.6KB, regs<=255).
//   Rationale: keeps rd10's two independent barrier domains per SM while
//   halving smem fragment traffic (4 warps x 8 frags vs 8 warps x 6 frags).
//   C[M,N](fp32) = concat-K GEMM + bias:
//     chunks 0..nc1-1       : A = pA1 (ldA1), B = pB1 (ldB1), K off kbase+c*64
//     chunks nc1..nc1+nc2-1 : A = pA2 (ldA2), B = pB2 (ldB2)
//   ksplit != 0: blockIdx.x = K-slice (n0=0, out += slice*sliceStride,
//                kbase = slice*nc1*64)
// ---------------------------------------------------------------------------
#define NTHR    128
#define BKH     64                    // halves per K chunk
#define LDTH    72                    // smem row stride (halves), +8 pad
#define TILE_H  (128 * LDTH)          // halves per matrix tile
#define STAGE_B (2 * TILE_H * 2)      // 36864 B per stage (A + B)
#define NSTG    3
#define LDE     132                   // epilogue smem stride (floats)

__global__ __launch_bounds__(NTHR, 2)
void fused_gemm(const __half* __restrict__ pA1, int ldA1,
                const __half* __restrict__ pB1, int ldB1,
                const __half* __restrict__ pA2, int ldA2,
                const __half* __restrict__ pB2, int ldB2,
                int nc1, int nc2,
                const float* __restrict__ bias,
                float* __restrict__ out, int ldC,
                int ksplit, int sliceStride)
{
    extern __shared__ __align__(16) char smem[];
    float* sb = (float*)smem;                      // bias tile [128]
    char*  stage_base = smem + 1024;
    const uint32_t stage_s = (uint32_t)__cvta_generic_to_shared(stage_base);

    const int tid  = threadIdx.x;
    const int warpId = tid >> 5;
    const int wm = warpId & 1;    // 0..1 (M dir, 64 rows)
    const int wn = warpId >> 1;   // 0..1 (N dir, 64 cols)
    const int m0 = blockIdx.y * 128;
    const int NC = nc1 + nc2;

    int n0, kbase;
    float* outp = out;
    if (ksplit) {
        n0 = 0;
        kbase = blockIdx.x * nc1 * BKH;
        outp  = out + (size_t)blockIdx.x * sliceStride;
    } else {
        n0 = blockIdx.x * 128;
        kbase = 0;
    }

    for (int i = tid; i < 128; i += NTHR)
        sb[i] = bias ? bias[n0 + i] : 0.0f;

    wmma::fragment<wmma::accumulator, 16, 16, 16, float> acc[4][4];
#pragma unroll
    for (int i = 0; i < 4; i++)
#pragma unroll
        for (int j = 0; j < 4; j++)
            wmma::fill_fragment(acc[i][j], 0.0f);

    // ---- async load of one K-chunk (A[128x64h] + B[128x64h]) into stage st ----
    auto load_chunk = [&](int c, int st) {
        const __half* bA; int lda; const __half* bB; int ldb; int kof;
        if (c < nc1) { bA = pA1; lda = ldA1; bB = pB1; ldb = ldB1; kof = kbase + c * BKH; }
        else         { bA = pA2; lda = ldA2; bB = pB2; ldb = ldB2; kof = (c - nc1) * BKH; }
        uint32_t sA = stage_s + st * STAGE_B;
        uint32_t sB = sA + TILE_H * 2;
#pragma unroll
        for (int it = 0; it < 8; it++) {
            int idx = tid + it * NTHR;   // 0..1023 : 128 rows x 8 segs(16B)
            int row = idx >> 3;
            int sg  = idx & 7;
            cpa16(sA + (uint32_t)(row * LDTH + sg * 8) * 2,
                  bA + (size_t)(m0 + row) * lda + kof + sg * 8);
            cpa16(sB + (uint32_t)(row * LDTH + sg * 8) * 2,
                  bB + (size_t)(n0 + row) * ldb + kof + sg * 8);
        }
        CP_COMMIT();
    };

    // prologue: 2 chunks in flight
    load_chunk(0, 0);
    load_chunk(1, 1);

    int st_c = 0, st_l = 2;
    for (int c = 0; c < NC; c++) {
        CP_WAIT1();
        __syncthreads();
        if (c + 2 < NC) {
            load_chunk(c + 2, st_l);
            if (++st_l == NSTG) st_l = 0;
        }

        const __half* As = (const __half*)(stage_base + st_c * STAGE_B);
        const __half* Bs = As + TILE_H;
        if (++st_c == NSTG) st_c = 0;

#pragma unroll
        for (int kk = 0; kk < BKH; kk += 16) {
            wmma::fragment<wmma::matrix_a, 16, 16, 16, __half, wmma::row_major> af[4];
            wmma::fragment<wmma::matrix_b, 16, 16, 16, __half, wmma::col_major> bf[4];
#pragma unroll
            for (int i = 0; i < 4; i++)
                wmma::load_matrix_sync(af[i], &As[(wm * 64 + i * 16) * LDTH + kk], LDTH);
#pragma unroll
            for (int j = 0; j < 4; j++)
                wmma::load_matrix_sync(bf[j], &Bs[(wn * 64 + j * 16) * LDTH + kk], LDTH);
#pragma unroll
            for (int i = 0; i < 4; i++)
#pragma unroll
                for (int j = 0; j < 4; j++)
                    wmma::mma_sync(acc[i][j], af[i], bf[j], acc[i][j]);
        }
    }

    // ---- epilogue: frags -> smem(fp32) -> +bias -> coalesced float4 stores ----
    __syncthreads();
    float* sE = (float*)stage_base;    // 128 x LDE floats = 67.6KB, fits stages
#pragma unroll
    for (int i = 0; i < 4; i++)
#pragma unroll
        for (int j = 0; j < 4; j++)
            wmma::store_matrix_sync(&sE[(wm * 64 + i * 16) * LDE + wn * 64 + j * 16],
                                    acc[i][j], LDE, wmma::mem_row_major);
    __syncthreads();

#pragma unroll
    for (int it = 0; it < 32; it++) {
        int i4  = tid + it * NTHR;     // 0..4095 float4s (128 rows x 32)
        int row = i4 >> 5;
        int c4  = i4 & 31;
        float4 v = *(const float4*)&sE[row * LDE + c4 * 4];
        v.x += sb[c4 * 4 + 0];
        v.y += sb[c4 * 4 + 1];
        v.z += sb[c4 * 4 + 2];
        v.w += sb[c4 * 4 + 3];
        *(float4*)(outp + (size_t)(m0 + row) * ldC + n0 + c4 * 4) = v;
    }
}

// ---------------------------------------------------------------------------
// fp32 -> fp16 convert copy: 8 elems/thread
// ---------------------------------------------------------------------------
__global__ __launch_bounds__(256)
void to_half_kernel(const float* __restrict__ src, __half* __restrict__ dst, int n8)
{
    int i = blockIdx.x * 256 + threadIdx.x;
    if (i < n8) {
        const float4* s = (const float4*)(src + (size_t)i * 8);
        float4 a = s[0], b = s[1];
        __half2 h[4];
        h[0] = __floats2half2_rn(a.x, a.y);
        h[1] = __floats2half2_rn(a.z, a.w);
        h[2] = __floats2half2_rn(b.x, b.y);
        h[3] = __floats2half2_rn(b.z, b.w);
        *(uint4*)(dst + (size_t)i * 8) = *(uint4*)h;
    }
}

// ---------------------------------------------------------------------------
// Repack + convert B: Bfh[n][e*16+r] = fp16(Bw[e][n][r])
// ---------------------------------------------------------------------------
__global__ __launch_bounds__(256)
void repack_B_kernel(const float* __restrict__ Bw, __half* __restrict__ Bfh)
{
    int idx = blockIdx.x * 256 + threadIdx.x;   // over 4096 * 32 groups of 4
    int n  = idx >> 5;
    int j4 = idx & 31;
    int j  = j4 * 4;
    int e  = j >> 4;
    int r  = j & 15;
    float4 v = *(const float4*)(Bw + (size_t)e * (D_OUTc * RANKD) + (size_t)n * RANKD + r);
    __half2 h[2];
    h[0] = __floats2half2_rn(v.x, v.y);
    h[1] = __floats2half2_rn(v.z, v.w);
    *(uint2*)(Bfh + (size_t)n * ERD + j) = *(uint2*)h;
}

// ---------------------------------------------------------------------------
// Router: logits = x @ Wr^T (fp32), top-2 softmax;
// h'fp16 = fp16(sum_s hp[s] * wv[e] * SCALING)
// ---------------------------------------------------------------------------
__global__ __launch_bounds__(256)
void router_kernel(const float* __restrict__ x,
                   const float* __restrict__ Wr,
                   const float* __restrict__ hp,   // [KSPLIT][T][128]
                   __half* __restrict__ h,
                   int T)
{
    const int t = blockIdx.x;
    const float* xr = x + (size_t)t * D_INc;

    float acc[NEXP];
#pragma unroll
    for (int e = 0; e < NEXP; e++) acc[e] = 0.0f;
    for (int j = threadIdx.x; j < D_INc; j += 256) {
        float xv = xr[j];
#pragma unroll
        for (int e = 0; e < NEXP; e++) acc[e] += xv * Wr[e * D_INc + j];
    }
#pragma unroll
    for (int off = 16; off > 0; off >>= 1)
#pragma unroll
        for (int e = 0; e < NEXP; e++) acc[e] += __shfl_xor_sync(0xffffffffu, acc[e], off);

    __shared__ float sred[8][NEXP];
    const int warp = threadIdx.x >> 5;
    const int lane = threadIdx.x & 31;
    if (lane == 0)
#pragma unroll
        for (int e = 0; e < NEXP; e++) sred[warp][e] = acc[e];
    __syncthreads();

    __shared__ float wv[NEXP];
    if (threadIdx.x == 0) {
        float l[NEXP];
#pragma unroll
        for (int e = 0; e < NEXP; e++) {
            float s = 0.0f;
#pragma unroll
            for (int w = 0; w < 8; w++) s += sred[w][e];
            l[e] = s;
        }
        int i0 = 0;
#pragma unroll
        for (int e = 1; e < NEXP; e++) if (l[e] > l[i0]) i0 = e;
        int i1 = -1;
#pragma unroll
        for (int e = 0; e < NEXP; e++) {
            if (e == i0) continue;
            if (i1 < 0 || l[e] > l[i1]) i1 = e;
        }
        float m  = l[i0];
        float e0 = expf(l[i0] - m);
        float e1 = expf(l[i1] - m);
        float s  = e0 + e1;
#pragma unroll
        for (int e = 0; e < NEXP; e++) wv[e] = 0.0f;
        wv[i0] = e0 / s;
        wv[i1] = e1 / s;
    }
    __syncthreads();

    if (threadIdx.x < ERD) {
        int e = threadIdx.x >> 4;
        size_t base = (size_t)t * ERD + threadIdx.x;
        size_t ss = (size_t)T * ERD;
        float v = hp[base] + hp[base + ss] + hp[base + 2 * ss] + hp[base + 3 * ss];
        h[base] = __float2half_rn(v * (wv[e] * SCALINGF));
    }
}

// ---------------------------------------------------------------------------
extern "C" void kernel_launch(void* const* d_in, const int* in_sizes, int n_in,
                              void* d_out, int out_size)
{
    const float* x  = (const float*)d_in[0];   // [T, 4096]
    const float* Wb = (const float*)d_in[1];   // [4096, 4096]
    const float* bb = (const float*)d_in[2];   // [4096]
    const float* Wr = (const float*)d_in[3];   // [8, 4096]
    const float* Aw = (const float*)d_in[4];   // [8,16,4096] == [128,4096]
    const float* Bw = (const float*)d_in[5];   // [8,4096,16]
    float* out = (float*)d_out;

    const int T = in_sizes[0] / D_INc;         // 8192

    __half *xh, *wbh, *ah, *bfh, *hh;
    float  *hp;
    cudaGetSymbolAddress((void**)&xh,  g_xh);
    cudaGetSymbolAddress((void**)&wbh, g_Wbh);
    cudaGetSymbolAddress((void**)&ah,  g_Ah);
    cudaGetSymbolAddress((void**)&bfh, g_Bfh);
    cudaGetSymbolAddress((void**)&hh,  g_hh);
    cudaGetSymbolAddress((void**)&hp,  g_hp);

    constexpr int SMEM = 1024 + NSTG * STAGE_B;   // 111,616 B

    static bool attr_done = false;
    if (!attr_done) {
        cudaFuncSetAttribute(fused_gemm, cudaFuncAttributeMaxDynamicSharedMemorySize, SMEM);
        attr_done = true;
    }

    // --- prepass: fp16 conversions ---
    {
        int n8x = T * D_INc / 8;
        to_half_kernel<<<(n8x + 255) / 256, 256>>>(x, xh, n8x);
        int n8w = D_OUTc * D_INc / 8;
        to_half_kernel<<<(n8w + 255) / 256, 256>>>(Wb, wbh, n8w);
        int n8a = ERD * D_INc / 8;
        to_half_kernel<<<(n8a + 255) / 256, 256>>>(Aw, ah, n8a);
        repack_B_kernel<<<(D_OUTc * 32) / 256, 256>>>(Bw, bfh);
    }

    // --- h partials = x @ A^T, split-K across 4 slices (grid 4 x 64) ---
    fused_gemm<<<dim3(KSPLIT, T / 128), NTHR, SMEM>>>(
        xh, D_INc, ah, D_INc,
        xh, D_INc, ah, D_INc,
        D_INc / BKH / KSPLIT, 0, nullptr, hp, ERD,
        1, T * ERD);

    // --- router: top-2 softmax weights, reduce partials, scale h' -> fp16 ---
    router_kernel<<<T, 256>>>(x, Wr, hp, hh, T);

    // --- out = [x | h'] @ [Wb | Bf]^T + bias ---
    fused_gemm<<<dim3(D_OUTc / 128, T / 128), NTHR, SMEM>>>(
        xh, D_INc, wbh, D_INc,
        hh, ERD, bfh, ERD,
        D_INc / BKH, ERD / BKH, bb, out, D_OUTc,
        0, 0);
}

// round 15
// speedup vs baseline: 1.0669x; 1.0342x over previous
#include <cuda_runtime.h>
#include <cuda_fp16.h>
#include <mma.h>
#include <cstdint>

using namespace nvcuda;

#define D_INc   4096
#define D_OUTc  4096
#define NEXP    8
#define RANKD   16
#define ERD     128          // NEXP * RANKD
#define SCALINGF 2.0f
#define T_MAXc  8192
#define KSPLIT  4

// scratch: fp16 operand copies + fp32 split-K partials + router weights
__device__ __half g_xh [T_MAXc * D_INc];          // 64MB
__device__ __half g_Wbh[D_OUTc * D_INc];          // 32MB
__device__ __half g_Ah [ERD * D_INc];             // 1MB
__device__ __half g_Bfh[D_OUTc * ERD];            // 1MB  repacked B_flat
__device__ __half g_hh [T_MAXc * ERD];            // 2MB  weighted h'
__device__ float  g_hp [KSPLIT * T_MAXc * ERD];   // 16MB h partials
__device__ float  g_wv [T_MAXc * NEXP];           // 256KB per-token expert weights

// ---------------------------------------------------------------------------
// cp.async helpers
// ---------------------------------------------------------------------------
__device__ __forceinline__ void cpa16(uint32_t dst, const void* src) {
    asm volatile("cp.async.cg.shared.global [%0], [%1], 16;" :: "r"(dst), "l"(src));
}
#define CP_COMMIT() asm volatile("cp.async.commit_group;")
#define CP_WAIT1()  asm volatile("cp.async.wait_group 1;")

// ---------------------------------------------------------------------------
// Fused tiled WMMA FP16 GEMM (fp32 accum), 3-stage cp.async pipeline.
//   (round-10 champion configuration — byte-identical mainloop)
//   Block tile 128x128, BK=64 halves, 256 threads (8 warps, warp 64x32),
//   2 CTAs/SM (regs<=128, smem 111.6KB).
// ---------------------------------------------------------------------------
#define BKH     64                    // halves per K chunk
#define LDTH    72                    // smem row stride (halves), +8 pad
#define TILE_H  (128 * LDTH)          // halves per matrix tile
#define STAGE_B (2 * TILE_H * 2)      // 36864 B per stage (A + B)
#define NSTG    3
#define LDE     132                   // epilogue smem stride (floats)

__global__ __launch_bounds__(256, 2)
void fused_gemm(const __half* __restrict__ pA1, int ldA1,
                const __half* __restrict__ pB1, int ldB1,
                const __half* __restrict__ pA2, int ldA2,
                const __half* __restrict__ pB2, int ldB2,
                int nc1, int nc2,
                const float* __restrict__ bias,
                float* __restrict__ out, int ldC,
                int ksplit, int sliceStride)
{
    extern __shared__ __align__(16) char smem[];
    float* sb = (float*)smem;                      // bias tile [128]
    char*  stage_base = smem + 1024;
    const uint32_t stage_s = (uint32_t)__cvta_generic_to_shared(stage_base);

    const int tid  = threadIdx.x;
    const int warpId = tid >> 5;
    const int wm = warpId & 1;    // 0..1 (M dir, 64 rows)
    const int wn = warpId >> 1;   // 0..3 (N dir, 32 cols)
    const int m0 = blockIdx.y * 128;
    const int NC = nc1 + nc2;

    int n0, kbase;
    float* outp = out;
    if (ksplit) {
        n0 = 0;
        kbase = blockIdx.x * nc1 * BKH;
        outp  = out + (size_t)blockIdx.x * sliceStride;
    } else {
        n0 = blockIdx.x * 128;
        kbase = 0;
    }

    for (int i = tid; i < 128; i += 256)
        sb[i] = bias ? bias[n0 + i] : 0.0f;

    wmma::fragment<wmma::accumulator, 16, 16, 16, float> acc[4][2];
#pragma unroll
    for (int i = 0; i < 4; i++)
#pragma unroll
        for (int j = 0; j < 2; j++)
            wmma::fill_fragment(acc[i][j], 0.0f);

    // ---- async load of one K-chunk (A[128x64h] + B[128x64h]) into stage st ----
    auto load_chunk = [&](int c, int st) {
        const __half* bA; int lda; const __half* bB; int ldb; int kof;
        if (c < nc1) { bA = pA1; lda = ldA1; bB = pB1; ldb = ldB1; kof = kbase + c * BKH; }
        else         { bA = pA2; lda = ldA2; bB = pB2; ldb = ldB2; kof = (c - nc1) * BKH; }
        uint32_t sA = stage_s + st * STAGE_B;
        uint32_t sB = sA + TILE_H * 2;
#pragma unroll
        for (int it = 0; it < 4; it++) {
            int idx = tid + it * 256;    // 0..1023 : 128 rows x 8 segs(16B)
            int row = idx >> 3;
            int sg  = idx & 7;
            cpa16(sA + (uint32_t)(row * LDTH + sg * 8) * 2,
                  bA + (size_t)(m0 + row) * lda + kof + sg * 8);
            cpa16(sB + (uint32_t)(row * LDTH + sg * 8) * 2,
                  bB + (size_t)(n0 + row) * ldb + kof + sg * 8);
        }
        CP_COMMIT();
    };

    // prologue: 2 chunks in flight
    load_chunk(0, 0);
    load_chunk(1, 1);

    int st_c = 0, st_l = 2;
    for (int c = 0; c < NC; c++) {
        CP_WAIT1();
        __syncthreads();
        if (c + 2 < NC) {
            load_chunk(c + 2, st_l);
            if (++st_l == NSTG) st_l = 0;
        }

        const __half* As = (const __half*)(stage_base + st_c * STAGE_B);
        const __half* Bs = As + TILE_H;
        if (++st_c == NSTG) st_c = 0;

#pragma unroll
        for (int kk = 0; kk < BKH; kk += 16) {
            wmma::fragment<wmma::matrix_a, 16, 16, 16, __half, wmma::row_major> af[4];
            wmma::fragment<wmma::matrix_b, 16, 16, 16, __half, wmma::col_major> bf[2];
#pragma unroll
            for (int i = 0; i < 4; i++)
                wmma::load_matrix_sync(af[i], &As[(wm * 64 + i * 16) * LDTH + kk], LDTH);
#pragma unroll
            for (int j = 0; j < 2; j++)
                wmma::load_matrix_sync(bf[j], &Bs[(wn * 32 + j * 16) * LDTH + kk], LDTH);
#pragma unroll
            for (int i = 0; i < 4; i++)
#pragma unroll
                for (int j = 0; j < 2; j++)
                    wmma::mma_sync(acc[i][j], af[i], bf[j], acc[i][j]);
        }
    }

    // ---- epilogue: frags -> smem(fp32) -> +bias -> coalesced float4 stores ----
    __syncthreads();
    float* sE = (float*)stage_base;    // 128 x LDE floats = 67.6KB, fits stages
#pragma unroll
    for (int i = 0; i < 4; i++)
#pragma unroll
        for (int j = 0; j < 2; j++)
            wmma::store_matrix_sync(&sE[(wm * 64 + i * 16) * LDE + wn * 32 + j * 16],
                                    acc[i][j], LDE, wmma::mem_row_major);
    __syncthreads();

#pragma unroll
    for (int it = 0; it < 16; it++) {
        int i4  = tid + it * 256;
        int row = i4 >> 5;
        int c4  = i4 & 31;
        float4 v = *(const float4*)&sE[row * LDE + c4 * 4];
        v.x += sb[c4 * 4 + 0];
        v.y += sb[c4 * 4 + 1];
        v.z += sb[c4 * 4 + 2];
        v.w += sb[c4 * 4 + 3];
        *(float4*)(outp + (size_t)(m0 + row) * ldC + n0 + c4 * 4) = v;
    }
}

// ---------------------------------------------------------------------------
// fp32 -> fp16 convert copy: 8 elems/thread
// ---------------------------------------------------------------------------
__global__ __launch_bounds__(256)
void to_half_kernel(const float* __restrict__ src, __half* __restrict__ dst, int n8)
{
    int i = blockIdx.x * 256 + threadIdx.x;
    if (i < n8) {
        const float4* s = (const float4*)(src + (size_t)i * 8);
        float4 a = s[0], b = s[1];
        __half2 h[4];
        h[0] = __floats2half2_rn(a.x, a.y);
        h[1] = __floats2half2_rn(a.z, a.w);
        h[2] = __floats2half2_rn(b.x, b.y);
        h[3] = __floats2half2_rn(b.z, b.w);
        *(uint4*)(dst + (size_t)i * 8) = *(uint4*)h;
    }
}

// ---------------------------------------------------------------------------
// Repack + convert B: Bfh[n][e*16+r] = fp16(Bw[e][n][r])
// ---------------------------------------------------------------------------
__global__ __launch_bounds__(256)
void repack_B_kernel(const float* __restrict__ Bw, __half* __restrict__ Bfh)
{
    int idx = blockIdx.x * 256 + threadIdx.x;   // over 4096 * 32 groups of 4
    int n  = idx >> 5;
    int j4 = idx & 31;
    int j  = j4 * 4;
    int e  = j >> 4;
    int r  = j & 15;
    float4 v = *(const float4*)(Bw + (size_t)e * (D_OUTc * RANKD) + (size_t)n * RANKD + r);
    __half2 h[2];
    h[0] = __floats2half2_rn(v.x, v.y);
    h[1] = __floats2half2_rn(v.z, v.w);
    *(uint2*)(Bfh + (size_t)n * ERD + j) = *(uint2*)h;
}

// ---------------------------------------------------------------------------
// Router weights only: logits = x @ Wr^T (fp32), top-2 softmax -> wv[t][8]
// (identical math to the rd10 router; the hp-reduction moved to scale_h)
// ---------------------------------------------------------------------------
__global__ __launch_bounds__(256)
void router_weights_kernel(const float* __restrict__ x,
                           const float* __restrict__ Wr,
                           float* __restrict__ wvout)
{
    const int t = blockIdx.x;
    const float* xr = x + (size_t)t * D_INc;

    float acc[NEXP];
#pragma unroll
    for (int e = 0; e < NEXP; e++) acc[e] = 0.0f;
    for (int j = threadIdx.x; j < D_INc; j += 256) {
        float xv = xr[j];
#pragma unroll
        for (int e = 0; e < NEXP; e++) acc[e] += xv * Wr[e * D_INc + j];
    }
#pragma unroll
    for (int off = 16; off > 0; off >>= 1)
#pragma unroll
        for (int e = 0; e < NEXP; e++) acc[e] += __shfl_xor_sync(0xffffffffu, acc[e], off);

    __shared__ float sred[8][NEXP];
    const int warp = threadIdx.x >> 5;
    const int lane = threadIdx.x & 31;
    if (lane == 0)
#pragma unroll
        for (int e = 0; e < NEXP; e++) sred[warp][e] = acc[e];
    __syncthreads();

    if (threadIdx.x == 0) {
        float l[NEXP];
#pragma unroll
        for (int e = 0; e < NEXP; e++) {
            float s = 0.0f;
#pragma unroll
            for (int w = 0; w < 8; w++) s += sred[w][e];
            l[e] = s;
        }
        // top-2, first occurrence on ties (matches jax.lax.top_k)
        int i0 = 0;
#pragma unroll
        for (int e = 1; e < NEXP; e++) if (l[e] > l[i0]) i0 = e;
        int i1 = -1;
#pragma unroll
        for (int e = 0; e < NEXP; e++) {
            if (e == i0) continue;
            if (i1 < 0 || l[e] > l[i1]) i1 = e;
        }
        float m  = l[i0];
        float e0 = expf(l[i0] - m);
        float e1 = expf(l[i1] - m);
        float s  = e0 + e1;
        float w[NEXP];
#pragma unroll
        for (int e = 0; e < NEXP; e++) w[e] = 0.0f;
        w[i0] = e0 / s;
        w[i1] = e1 / s;
#pragma unroll
        for (int e = 0; e < NEXP; e++) wvout[t * NEXP + e] = w[e];
    }
}

// ---------------------------------------------------------------------------
// scale_h: h'fp16[t,j] = fp16( (sum_s hp[s][t][j]) * wv[t][j>>4] * SCALING )
// ---------------------------------------------------------------------------
__global__ __launch_bounds__(256)
void scale_h_kernel(const float* __restrict__ hp,
                    const float* __restrict__ wv,
                    __half* __restrict__ h,
                    int T)
{
    int idx = blockIdx.x * 256 + threadIdx.x;    // over T*128
    int t = idx >> 7;
    int e = (idx >> 4) & 7;
    size_t ss = (size_t)T * ERD;
    float v = hp[idx] + hp[idx + ss] + hp[idx + 2 * ss] + hp[idx + 3 * ss];
    h[idx] = __float2half_rn(v * (wv[t * NEXP + e] * SCALINGF));
}

// ---------------------------------------------------------------------------
extern "C" void kernel_launch(void* const* d_in, const int* in_sizes, int n_in,
                              void* d_out, int out_size)
{
    const float* x  = (const float*)d_in[0];   // [T, 4096]
    const float* Wb = (const float*)d_in[1];   // [4096, 4096]
    const float* bb = (const float*)d_in[2];   // [4096]
    const float* Wr = (const float*)d_in[3];   // [8, 4096]
    const float* Aw = (const float*)d_in[4];   // [8,16,4096] == [128,4096]
    const float* Bw = (const float*)d_in[5];   // [8,4096,16]
    float* out = (float*)d_out;

    const int T = in_sizes[0] / D_INc;         // 8192

    __half *xh, *wbh, *ah, *bfh, *hh;
    float  *hp, *wv;
    cudaGetSymbolAddress((void**)&xh,  g_xh);
    cudaGetSymbolAddress((void**)&wbh, g_Wbh);
    cudaGetSymbolAddress((void**)&ah,  g_Ah);
    cudaGetSymbolAddress((void**)&bfh, g_Bfh);
    cudaGetSymbolAddress((void**)&hh,  g_hh);
    cudaGetSymbolAddress((void**)&hp,  g_hp);
    cudaGetSymbolAddress((void**)&wv,  g_wv);

    constexpr int SMEM = 1024 + NSTG * STAGE_B;   // 111,616 B

    static bool init_done = false;
    static cudaStream_t s2 = nullptr;
    static cudaEvent_t  eFork = nullptr, eJoin = nullptr;
    if (!init_done) {
        cudaFuncSetAttribute(fused_gemm, cudaFuncAttributeMaxDynamicSharedMemorySize, SMEM);
        cudaStreamCreateWithFlags(&s2, cudaStreamNonBlocking);
        cudaEventCreateWithFlags(&eFork, cudaEventDisableTiming);
        cudaEventCreateWithFlags(&eJoin, cudaEventDisableTiming);
        init_done = true;
    }

    // ---- fork: independent chain {router weights, Wb->fp16, B repack} on s2 ----
    cudaEventRecord(eFork, 0);
    cudaStreamWaitEvent(s2, eFork, 0);

    router_weights_kernel<<<T, 256, 0, s2>>>(x, Wr, wv);
    {
        int n8w = D_OUTc * D_INc / 8;
        to_half_kernel<<<(n8w + 255) / 256, 256, 0, s2>>>(Wb, wbh, n8w);
        repack_B_kernel<<<(D_OUTc * 32) / 256, 256, 0, s2>>>(Bw, bfh);
    }
    cudaEventRecord(eJoin, s2);

    // ---- main chain on stream 0: A->fp16, x->fp16, h partials ----
    {
        int n8a = ERD * D_INc / 8;
        to_half_kernel<<<(n8a + 255) / 256, 256>>>(Aw, ah, n8a);
        int n8x = T * D_INc / 8;
        to_half_kernel<<<(n8x + 255) / 256, 256>>>(x, xh, n8x);
    }
    fused_gemm<<<dim3(KSPLIT, T / 128), 256, SMEM>>>(
        xh, D_INc, ah, D_INc,
        xh, D_INc, ah, D_INc,
        D_INc / BKH / KSPLIT, 0, nullptr, hp, ERD,
        1, T * ERD);

    // ---- join, then weighted h' and the fused big GEMM ----
    cudaStreamWaitEvent(0, eJoin, 0);
    scale_h_kernel<<<(T * ERD) / 256, 256>>>(hp, wv, hh, T);

    fused_gemm<<<dim3(D_OUTc / 128, T / 128), 256, SMEM>>>(
        xh, D_INc, wbh, D_INc,
        hh, ERD, bfh, ERD,
        D_INc / BKH, ERD / BKH, bb, out, D_OUTc,
        0, 0);
}

// round 16
// speedup vs baseline: 1.0869x; 1.0187x over previous
#include <cuda_runtime.h>
#include <cuda_fp16.h>
#include <mma.h>
#include <cstdint>

using namespace nvcuda;

#define D_INc   4096
#define D_OUTc  4096
#define NEXP    8
#define RANKD   16
#define ERD     128          // NEXP * RANKD
#define SCALINGF 2.0f
#define T_MAXc  8192
#define KSPLIT  4

// scratch: fp16 operand copies + fp32 split-K partials + router weights
__device__ __half g_xh [T_MAXc * D_INc];          // 64MB
__device__ __half g_Wbh[D_OUTc * D_INc];          // 32MB
__device__ __half g_Ah [ERD * D_INc];             // 1MB
__device__ __half g_Bfh[D_OUTc * ERD];            // 1MB  repacked B_flat
__device__ __half g_hh [T_MAXc * ERD];            // 2MB  weighted h'
__device__ float  g_hp [KSPLIT * T_MAXc * ERD];   // 16MB h partials
__device__ float  g_wv [T_MAXc * NEXP];           // 256KB per-token expert weights

// ---------------------------------------------------------------------------
// cp.async helpers
// ---------------------------------------------------------------------------
__device__ __forceinline__ void cpa16(uint32_t dst, const void* src) {
    asm volatile("cp.async.cg.shared.global [%0], [%1], 16;" :: "r"(dst), "l"(src));
}
#define CP_COMMIT() asm volatile("cp.async.commit_group;")
#define CP_WAIT1()  asm volatile("cp.async.wait_group 1;")
#define CP_WAIT0()  asm volatile("cp.async.wait_group 0;")

// ---------------------------------------------------------------------------
// Fused tiled WMMA FP16 GEMM (fp32 accum), 3-stage cp.async pipeline.
//   rd10 champion config: block 128x128, BK=64 halves, 256 threads
//   (8 warps, warp 64x32), 2 CTAs/SM (regs<=128, smem 111.6KB).
//   rd16 delta: prefetch cp.async issues interleaved into the 4 k-steps
//   (smem write-port smoothing) + exact tail wait.
// ---------------------------------------------------------------------------
#define BKH     64                    // halves per K chunk
#define LDTH    72                    // smem row stride (halves), +8 pad
#define TILE_H  (128 * LDTH)          // halves per matrix tile
#define STAGE_B (2 * TILE_H * 2)      // 36864 B per stage (A + B)
#define NSTG    3
#define LDE     132                   // epilogue smem stride (floats)

__global__ __launch_bounds__(256, 2)
void fused_gemm(const __half* __restrict__ pA1, int ldA1,
                const __half* __restrict__ pB1, int ldB1,
                const __half* __restrict__ pA2, int ldA2,
                const __half* __restrict__ pB2, int ldB2,
                int nc1, int nc2,
                const float* __restrict__ bias,
                float* __restrict__ out, int ldC,
                int ksplit, int sliceStride)
{
    extern __shared__ __align__(16) char smem[];
    float* sb = (float*)smem;                      // bias tile [128]
    char*  stage_base = smem + 1024;
    const uint32_t stage_s = (uint32_t)__cvta_generic_to_shared(stage_base);

    const int tid  = threadIdx.x;
    const int warpId = tid >> 5;
    const int wm = warpId & 1;    // 0..1 (M dir, 64 rows)
    const int wn = warpId >> 1;   // 0..3 (N dir, 32 cols)
    const int m0 = blockIdx.y * 128;
    const int NC = nc1 + nc2;

    int n0, kbase;
    float* outp = out;
    if (ksplit) {
        n0 = 0;
        kbase = blockIdx.x * nc1 * BKH;
        outp  = out + (size_t)blockIdx.x * sliceStride;
    } else {
        n0 = blockIdx.x * 128;
        kbase = 0;
    }

    for (int i = tid; i < 128; i += 256)
        sb[i] = bias ? bias[n0 + i] : 0.0f;

    wmma::fragment<wmma::accumulator, 16, 16, 16, float> acc[4][2];
#pragma unroll
    for (int i = 0; i < 4; i++)
#pragma unroll
        for (int j = 0; j < 2; j++)
            wmma::fill_fragment(acc[i][j], 0.0f);

    // ---- full-chunk async load (prologue only) ----
    auto load_chunk = [&](int c, int st) {
        const __half* bA; int lda; const __half* bB; int ldb; int kof;
        if (c < nc1) { bA = pA1; lda = ldA1; bB = pB1; ldb = ldB1; kof = kbase + c * BKH; }
        else         { bA = pA2; lda = ldA2; bB = pB2; ldb = ldB2; kof = (c - nc1) * BKH; }
        uint32_t sA = stage_s + st * STAGE_B;
        uint32_t sB = sA + TILE_H * 2;
#pragma unroll
        for (int it = 0; it < 4; it++) {
            int idx = tid + it * 256;    // 0..1023 : 128 rows x 8 segs(16B)
            int row = idx >> 3;
            int sg  = idx & 7;
            cpa16(sA + (uint32_t)(row * LDTH + sg * 8) * 2,
                  bA + (size_t)(m0 + row) * lda + kof + sg * 8);
            cpa16(sB + (uint32_t)(row * LDTH + sg * 8) * 2,
                  bB + (size_t)(n0 + row) * ldb + kof + sg * 8);
        }
        CP_COMMIT();
    };

    // prologue: 2 chunks in flight
    load_chunk(0, 0);
    load_chunk(1, 1);

    int st_c = 0, st_l = 2;
    for (int c = 0; c < NC; c++) {
        if (c + 1 == NC) { CP_WAIT0(); } else { CP_WAIT1(); }
        __syncthreads();

        // prefetch-pointer setup for chunk c+2 (issues interleaved below)
        const bool pf = (c + 2 < NC);
        const __half* pbA = pA1; int plda = ldA1;
        const __half* pbB = pB1; int pldb = ldB1;
        int pkof = 0;
        uint32_t psA = 0, psB = 0;
        if (pf) {
            int cc = c + 2;
            if (cc < nc1) { pbA = pA1; plda = ldA1; pbB = pB1; pldb = ldB1; pkof = kbase + cc * BKH; }
            else          { pbA = pA2; plda = ldA2; pbB = pB2; pldb = ldB2; pkof = (cc - nc1) * BKH; }
            psA = stage_s + st_l * STAGE_B;
            psB = psA + TILE_H * 2;
        }

        const __half* As = (const __half*)(stage_base + st_c * STAGE_B);
        const __half* Bs = As + TILE_H;
        if (++st_c == NSTG) st_c = 0;

#pragma unroll
        for (int ks = 0; ks < 4; ks++) {
            const int kk = ks * 16;
            // interleaved prefetch: 2 cp.async per thread per k-step
            if (pf) {
                int idx = tid + ks * 256;
                int row = idx >> 3;
                int sg  = idx & 7;
                cpa16(psA + (uint32_t)(row * LDTH + sg * 8) * 2,
                      pbA + (size_t)(m0 + row) * plda + pkof + sg * 8);
                cpa16(psB + (uint32_t)(row * LDTH + sg * 8) * 2,
                      pbB + (size_t)(n0 + row) * pldb + pkof + sg * 8);
            }

            wmma::fragment<wmma::matrix_a, 16, 16, 16, __half, wmma::row_major> af[4];
            wmma::fragment<wmma::matrix_b, 16, 16, 16, __half, wmma::col_major> bf[2];
#pragma unroll
            for (int i = 0; i < 4; i++)
                wmma::load_matrix_sync(af[i], &As[(wm * 64 + i * 16) * LDTH + kk], LDTH);
#pragma unroll
            for (int j = 0; j < 2; j++)
                wmma::load_matrix_sync(bf[j], &Bs[(wn * 32 + j * 16) * LDTH + kk], LDTH);
#pragma unroll
            for (int i = 0; i < 4; i++)
#pragma unroll
                for (int j = 0; j < 2; j++)
                    wmma::mma_sync(acc[i][j], af[i], bf[j], acc[i][j]);
        }

        if (pf) {
            CP_COMMIT();
            if (++st_l == NSTG) st_l = 0;
        }
    }

    // ---- epilogue: frags -> smem(fp32) -> +bias -> coalesced float4 stores ----
    __syncthreads();
    float* sE = (float*)stage_base;    // 128 x LDE floats = 67.6KB, fits stages
#pragma unroll
    for (int i = 0; i < 4; i++)
#pragma unroll
        for (int j = 0; j < 2; j++)
            wmma::store_matrix_sync(&sE[(wm * 64 + i * 16) * LDE + wn * 32 + j * 16],
                                    acc[i][j], LDE, wmma::mem_row_major);
    __syncthreads();

#pragma unroll
    for (int it = 0; it < 16; it++) {
        int i4  = tid + it * 256;
        int row = i4 >> 5;
        int c4  = i4 & 31;
        float4 v = *(const float4*)&sE[row * LDE + c4 * 4];
        v.x += sb[c4 * 4 + 0];
        v.y += sb[c4 * 4 + 1];
        v.z += sb[c4 * 4 + 2];
        v.w += sb[c4 * 4 + 3];
        *(float4*)(outp + (size_t)(m0 + row) * ldC + n0 + c4 * 4) = v;
    }
}

// ---------------------------------------------------------------------------
// fp32 -> fp16 convert copy: 8 elems/thread
// ---------------------------------------------------------------------------
__global__ __launch_bounds__(256)
void to_half_kernel(const float* __restrict__ src, __half* __restrict__ dst, int n8)
{
    int i = blockIdx.x * 256 + threadIdx.x;
    if (i < n8) {
        const float4* s = (const float4*)(src + (size_t)i * 8);
        float4 a = s[0], b = s[1];
        __half2 h[4];
        h[0] = __floats2half2_rn(a.x, a.y);
        h[1] = __floats2half2_rn(a.z, a.w);
        h[2] = __floats2half2_rn(b.x, b.y);
        h[3] = __floats2half2_rn(b.z, b.w);
        *(uint4*)(dst + (size_t)i * 8) = *(uint4*)h;
    }
}

// ---------------------------------------------------------------------------
// Repack + convert B: Bfh[n][e*16+r] = fp16(Bw[e][n][r])
// ---------------------------------------------------------------------------
__global__ __launch_bounds__(256)
void repack_B_kernel(const float* __restrict__ Bw, __half* __restrict__ Bfh)
{
    int idx = blockIdx.x * 256 + threadIdx.x;   // over 4096 * 32 groups of 4
    int n  = idx >> 5;
    int j4 = idx & 31;
    int j  = j4 * 4;
    int e  = j >> 4;
    int r  = j & 15;
    float4 v = *(const float4*)(Bw + (size_t)e * (D_OUTc * RANKD) + (size_t)n * RANKD + r);
    __half2 h[2];
    h[0] = __floats2half2_rn(v.x, v.y);
    h[1] = __floats2half2_rn(v.z, v.w);
    *(uint2*)(Bfh + (size_t)n * ERD + j) = *(uint2*)h;
}

// ---------------------------------------------------------------------------
// Router weights only: logits = x @ Wr^T (fp32), top-2 softmax -> wv[t][8]
// ---------------------------------------------------------------------------
__global__ __launch_bounds__(256)
void router_weights_kernel(const float* __restrict__ x,
                           const float* __restrict__ Wr,
                           float* __restrict__ wvout)
{
    const int t = blockIdx.x;
    const float* xr = x + (size_t)t * D_INc;

    float acc[NEXP];
#pragma unroll
    for (int e = 0; e < NEXP; e++) acc[e] = 0.0f;
    for (int j = threadIdx.x; j < D_INc; j += 256) {
        float xv = xr[j];
#pragma unroll
        for (int e = 0; e < NEXP; e++) acc[e] += xv * Wr[e * D_INc + j];
    }
#pragma unroll
    for (int off = 16; off > 0; off >>= 1)
#pragma unroll
        for (int e = 0; e < NEXP; e++) acc[e] += __shfl_xor_sync(0xffffffffu, acc[e], off);

    __shared__ float sred[8][NEXP];
    const int warp = threadIdx.x >> 5;
    const int lane = threadIdx.x & 31;
    if (lane == 0)
#pragma unroll
        for (int e = 0; e < NEXP; e++) sred[warp][e] = acc[e];
    __syncthreads();

    if (threadIdx.x == 0) {
        float l[NEXP];
#pragma unroll
        for (int e = 0; e < NEXP; e++) {
            float s = 0.0f;
#pragma unroll
            for (int w = 0; w < 8; w++) s += sred[w][e];
            l[e] = s;
        }
        // top-2, first occurrence on ties (matches jax.lax.top_k)
        int i0 = 0;
#pragma unroll
        for (int e = 1; e < NEXP; e++) if (l[e] > l[i0]) i0 = e;
        int i1 = -1;
#pragma unroll
        for (int e = 0; e < NEXP; e++) {
            if (e == i0) continue;
            if (i1 < 0 || l[e] > l[i1]) i1 = e;
        }
        float m  = l[i0];
        float e0 = expf(l[i0] - m);
        float e1 = expf(l[i1] - m);
        float s  = e0 + e1;
        float w[NEXP];
#pragma unroll
        for (int e = 0; e < NEXP; e++) w[e] = 0.0f;
        w[i0] = e0 / s;
        w[i1] = e1 / s;
#pragma unroll
        for (int e = 0; e < NEXP; e++) wvout[t * NEXP + e] = w[e];
    }
}

// ---------------------------------------------------------------------------
// scale_h: h'fp16[t,j] = fp16( (sum_s hp[s][t][j]) * wv[t][j>>4] * SCALING )
// ---------------------------------------------------------------------------
__global__ __launch_bounds__(256)
void scale_h_kernel(const float* __restrict__ hp,
                    const float* __restrict__ wv,
                    __half* __restrict__ h,
                    int T)
{
    int idx = blockIdx.x * 256 + threadIdx.x;    // over T*128
    int t = idx >> 7;
    int e = (idx >> 4) & 7;
    size_t ss = (size_t)T * ERD;
    float v = hp[idx] + hp[idx + ss] + hp[idx + 2 * ss] + hp[idx + 3 * ss];
    h[idx] = __float2half_rn(v * (wv[t * NEXP + e] * SCALINGF));
}

// ---------------------------------------------------------------------------
extern "C" void kernel_launch(void* const* d_in, const int* in_sizes, int n_in,
                              void* d_out, int out_size)
{
    const float* x  = (const float*)d_in[0];   // [T, 4096]
    const float* Wb = (const float*)d_in[1];   // [4096, 4096]
    const float* bb = (const float*)d_in[2];   // [4096]
    const float* Wr = (const float*)d_in[3];   // [8, 4096]
    const float* Aw = (const float*)d_in[4];   // [8,16,4096] == [128,4096]
    const float* Bw = (const float*)d_in[5];   // [8,4096,16]
    float* out = (float*)d_out;

    const int T = in_sizes[0] / D_INc;         // 8192

    __half *xh, *wbh, *ah, *bfh, *hh;
    float  *hp, *wv;
    cudaGetSymbolAddress((void**)&xh,  g_xh);
    cudaGetSymbolAddress((void**)&wbh, g_Wbh);
    cudaGetSymbolAddress((void**)&ah,  g_Ah);
    cudaGetSymbolAddress((void**)&bfh, g_Bfh);
    cudaGetSymbolAddress((void**)&hh,  g_hh);
    cudaGetSymbolAddress((void**)&hp,  g_hp);
    cudaGetSymbolAddress((void**)&wv,  g_wv);

    constexpr int SMEM = 1024 + NSTG * STAGE_B;   // 111,616 B

    static bool init_done = false;
    static cudaStream_t s2 = nullptr;
    static cudaEvent_t  eFork = nullptr, eJoin = nullptr;
    if (!init_done) {
        cudaFuncSetAttribute(fused_gemm, cudaFuncAttributeMaxDynamicSharedMemorySize, SMEM);
        cudaStreamCreateWithFlags(&s2, cudaStreamNonBlocking);
        cudaEventCreateWithFlags(&eFork, cudaEventDisableTiming);
        cudaEventCreateWithFlags(&eJoin, cudaEventDisableTiming);
        init_done = true;
    }

    // ---- fork: independent chain {router weights, Wb->fp16, B repack} on s2 ----
    cudaEventRecord(eFork, 0);
    cudaStreamWaitEvent(s2, eFork, 0);

    router_weights_kernel<<<T, 256, 0, s2>>>(x, Wr, wv);
    {
        int n8w = D_OUTc * D_INc / 8;
        to_half_kernel<<<(n8w + 255) / 256, 256, 0, s2>>>(Wb, wbh, n8w);
        repack_B_kernel<<<(D_OUTc * 32) / 256, 256, 0, s2>>>(Bw, bfh);
    }
    cudaEventRecord(eJoin, s2);

    // ---- main chain on stream 0: A->fp16, x->fp16, h partials ----
    {
        int n8a = ERD * D_INc / 8;
        to_half_kernel<<<(n8a + 255) / 256, 256>>>(Aw, ah, n8a);
        int n8x = T * D_INc / 8;
        to_half_kernel<<<(n8x + 255) / 256, 256>>>(x, xh, n8x);
    }
    fused_gemm<<<dim3(KSPLIT, T / 128), 256, SMEM>>>(
        xh, D_INc, ah, D_INc,
        xh, D_INc, ah, D_INc,
        D_INc / BKH / KSPLIT, 0, nullptr, hp, ERD,
        1, T * ERD);

    // ---- join, then weighted h' and the fused big GEMM ----
    cudaStreamWaitEvent(0, eJoin, 0);
    scale_h_kernel<<<(T * ERD) / 256, 256>>>(hp, wv, hh, T);

    fused_gemm<<<dim3(D_OUTc / 128, T / 128), 256, SMEM>>>(
        xh, D_INc, wbh, D_INc,
        hh, ERD, bfh, ERD,
        D_INc / BKH, ERD / BKH, bb, out, D_OUTc,
        0, 0);
}

// round 17
// speedup vs baseline: 1.0946x; 1.0071x over previous
#include <cuda_runtime.h>
#include <cuda_fp16.h>
#include <mma.h>
#include <cstdint>

using namespace nvcuda;

#define D_INc   4096
#define D_OUTc  4096
#define NEXP    8
#define RANKD   16
#define ERD     128          // NEXP * RANKD
#define SCALINGF 2.0f
#define T_MAXc  8192
#define KSPLIT  4

// scratch: fp16 operand copies + fp32 split-K partials + router weights
__device__ __half g_xh [T_MAXc * D_INc];          // 64MB
__device__ __half g_Wbh[D_OUTc * D_INc];          // 32MB
__device__ __half g_Ah [ERD * D_INc];             // 1MB
__device__ __half g_Bfh[D_OUTc * ERD];            // 1MB  repacked B_flat
__device__ __half g_hh [T_MAXc * ERD];            // 2MB  weighted h'
__device__ float  g_hp [KSPLIT * T_MAXc * ERD];   // 16MB h partials
__device__ float  g_wv [T_MAXc * NEXP];           // 256KB per-token expert weights

// ---------------------------------------------------------------------------
// cp.async helpers
// ---------------------------------------------------------------------------
__device__ __forceinline__ void cpa16(uint32_t dst, const void* src) {
    asm volatile("cp.async.cg.shared.global [%0], [%1], 16;" :: "r"(dst), "l"(src));
}
#define CP_COMMIT() asm volatile("cp.async.commit_group;")
#define CP_WAIT1()  asm volatile("cp.async.wait_group 1;")
#define CP_WAIT0()  asm volatile("cp.async.wait_group 0;")

// ---------------------------------------------------------------------------
// Fused tiled WMMA FP16 GEMM (fp32 accum), 3-stage cp.async pipeline.
//   rd10 champion mainloop + rd16 interleaved prefetch/tail wait.
//   rd17 delta: bias seeded into accumulators via one prologue MMA
//   (fp16-rounded bias, error ~1e-5 abs) and DIRECT fragment stores to
//   gmem — the smem epilogue roundtrip (2 syncs + 128KB/CTA) is gone.
//   Block tile 128x128, BK=64 halves, 256 threads (8 warps, warp 64x32),
//   2 CTAs/SM (regs<=128, smem 111.6KB).
// ---------------------------------------------------------------------------
#define BKH     64                    // halves per K chunk
#define LDTH    72                    // smem row stride (halves), +8 pad
#define TILE_H  (128 * LDTH)          // halves per matrix tile
#define STAGE_B (2 * TILE_H * 2)      // 36864 B per stage (A + B)
#define NSTG    3

__global__ __launch_bounds__(256, 2)
void fused_gemm(const __half* __restrict__ pA1, int ldA1,
                const __half* __restrict__ pB1, int ldB1,
                const __half* __restrict__ pA2, int ldA2,
                const __half* __restrict__ pB2, int ldB2,
                int nc1, int nc2,
                const float* __restrict__ bias,
                float* __restrict__ out, int ldC,
                int ksplit, int sliceStride)
{
    extern __shared__ __align__(16) char smem[];
    char*  stage_base = smem + 1024;
    const uint32_t stage_s = (uint32_t)__cvta_generic_to_shared(stage_base);

    const int tid  = threadIdx.x;
    const int warpId = tid >> 5;
    const int wm = warpId & 1;    // 0..1 (M dir, 64 rows)
    const int wn = warpId >> 1;   // 0..3 (N dir, 32 cols)
    const int m0 = blockIdx.y * 128;
    const int NC = nc1 + nc2;

    int n0, kbase;
    float* outp = out;
    if (ksplit) {
        n0 = 0;
        kbase = blockIdx.x * nc1 * BKH;
        outp  = out + (size_t)blockIdx.x * sliceStride;
    } else {
        n0 = blockIdx.x * 128;
        kbase = 0;
    }

    wmma::fragment<wmma::accumulator, 16, 16, 16, float> acc[4][2];
#pragma unroll
    for (int i = 0; i < 4; i++)
#pragma unroll
        for (int j = 0; j < 2; j++)
            wmma::fill_fragment(acc[i][j], 0.0f);

    // ---- bias seeding: acc[i][j] += e0_ones(16x16) @ biasRow (one MMA) ----
    // Uses the stage-2 smem region, which is untouched until chunk-2 prefetch.
    if (bias) {
        char*   st2p  = stage_base + 2 * STAGE_B;
        __half* sOnes = (__half*)st2p;            // 16x16 row_major, 512B
        __half* sB2   = (__half*)(st2p + 512);    // 16(k) x 128(n) col_major ld=16, 4KB
        for (int i = tid; i < 2304; i += 256)     // zero 4608 B
            ((__half*)st2p)[i] = __float2half(0.0f);
        __syncthreads();
        if (tid < 16)  sOnes[tid * 16] = __float2half(1.0f);   // A[i][0] = 1
        if (tid < 128) sB2[tid * 16]   = __float2half(bias[n0 + tid]); // B[0][n] = bias
        __syncthreads();
        wmma::fragment<wmma::matrix_a, 16, 16, 16, __half, wmma::row_major> a1;
        wmma::load_matrix_sync(a1, sOnes, 16);
#pragma unroll
        for (int j = 0; j < 2; j++) {
            wmma::fragment<wmma::matrix_b, 16, 16, 16, __half, wmma::col_major> bfb;
            wmma::load_matrix_sync(bfb, sB2 + (wn * 32 + j * 16) * 16, 16);
#pragma unroll
            for (int i = 0; i < 4; i++)
                wmma::mma_sync(acc[i][j], a1, bfb, acc[i][j]);
        }
        __syncthreads();   // all reads of st2 done before chunk-2 prefetch writes it
    }

    // ---- full-chunk async load (prologue only) ----
    auto load_chunk = [&](int c, int st) {
        const __half* bA; int lda; const __half* bB; int ldb; int kof;
        if (c < nc1) { bA = pA1; lda = ldA1; bB = pB1; ldb = ldB1; kof = kbase + c * BKH; }
        else         { bA = pA2; lda = ldA2; bB = pB2; ldb = ldB2; kof = (c - nc1) * BKH; }
        uint32_t sA = stage_s + st * STAGE_B;
        uint32_t sB = sA + TILE_H * 2;
#pragma unroll
        for (int it = 0; it < 4; it++) {
            int idx = tid + it * 256;    // 0..1023 : 128 rows x 8 segs(16B)
            int row = idx >> 3;
            int sg  = idx & 7;
            cpa16(sA + (uint32_t)(row * LDTH + sg * 8) * 2,
                  bA + (size_t)(m0 + row) * lda + kof + sg * 8);
            cpa16(sB + (uint32_t)(row * LDTH + sg * 8) * 2,
                  bB + (size_t)(n0 + row) * ldb + kof + sg * 8);
        }
        CP_COMMIT();
    };

    // prologue: 2 chunks in flight
    load_chunk(0, 0);
    load_chunk(1, 1);

    int st_c = 0, st_l = 2;
    for (int c = 0; c < NC; c++) {
        if (c + 1 == NC) { CP_WAIT0(); } else { CP_WAIT1(); }
        __syncthreads();

        // prefetch-pointer setup for chunk c+2 (issues interleaved below)
        const bool pf = (c + 2 < NC);
        const __half* pbA = pA1; int plda = ldA1;
        const __half* pbB = pB1; int pldb = ldB1;
        int pkof = 0;
        uint32_t psA = 0, psB = 0;
        if (pf) {
            int cc = c + 2;
            if (cc < nc1) { pbA = pA1; plda = ldA1; pbB = pB1; pldb = ldB1; pkof = kbase + cc * BKH; }
            else          { pbA = pA2; plda = ldA2; pbB = pB2; pldb = ldB2; pkof = (cc - nc1) * BKH; }
            psA = stage_s + st_l * STAGE_B;
            psB = psA + TILE_H * 2;
        }

        const __half* As = (const __half*)(stage_base + st_c * STAGE_B);
        const __half* Bs = As + TILE_H;
        if (++st_c == NSTG) st_c = 0;

#pragma unroll
        for (int ks = 0; ks < 4; ks++) {
            const int kk = ks * 16;
            // interleaved prefetch: 2 cp.async per thread per k-step
            if (pf) {
                int idx = tid + ks * 256;
                int row = idx >> 3;
                int sg  = idx & 7;
                cpa16(psA + (uint32_t)(row * LDTH + sg * 8) * 2,
                      pbA + (size_t)(m0 + row) * plda + pkof + sg * 8);
                cpa16(psB + (uint32_t)(row * LDTH + sg * 8) * 2,
                      pbB + (size_t)(n0 + row) * pldb + pkof + sg * 8);
            }

            wmma::fragment<wmma::matrix_a, 16, 16, 16, __half, wmma::row_major> af[4];
            wmma::fragment<wmma::matrix_b, 16, 16, 16, __half, wmma::col_major> bf[2];
#pragma unroll
            for (int i = 0; i < 4; i++)
                wmma::load_matrix_sync(af[i], &As[(wm * 64 + i * 16) * LDTH + kk], LDTH);
#pragma unroll
            for (int j = 0; j < 2; j++)
                wmma::load_matrix_sync(bf[j], &Bs[(wn * 32 + j * 16) * LDTH + kk], LDTH);
#pragma unroll
            for (int i = 0; i < 4; i++)
#pragma unroll
                for (int j = 0; j < 2; j++)
                    wmma::mma_sync(acc[i][j], af[i], bf[j], acc[i][j]);
        }

        if (pf) {
            CP_COMMIT();
            if (++st_l == NSTG) st_l = 0;
        }
    }

    // ---- epilogue: direct fragment stores to gmem (bias already in acc) ----
#pragma unroll
    for (int i = 0; i < 4; i++)
#pragma unroll
        for (int j = 0; j < 2; j++)
            wmma::store_matrix_sync(
                outp + (size_t)(m0 + wm * 64 + i * 16) * ldC + n0 + wn * 32 + j * 16,
                acc[i][j], ldC, wmma::mem_row_major);
}

// ---------------------------------------------------------------------------
// fp32 -> fp16 convert copy: 8 elems/thread
// ---------------------------------------------------------------------------
__global__ __launch_bounds__(256)
void to_half_kernel(const float* __restrict__ src, __half* __restrict__ dst, int n8)
{
    int i = blockIdx.x * 256 + threadIdx.x;
    if (i < n8) {
        const float4* s = (const float4*)(src + (size_t)i * 8);
        float4 a = s[0], b = s[1];
        __half2 h[4];
        h[0] = __floats2half2_rn(a.x, a.y);
        h[1] = __floats2half2_rn(a.z, a.w);
        h[2] = __floats2half2_rn(b.x, b.y);
        h[3] = __floats2half2_rn(b.z, b.w);
        *(uint4*)(dst + (size_t)i * 8) = *(uint4*)h;
    }
}

// ---------------------------------------------------------------------------
// Repack + convert B: Bfh[n][e*16+r] = fp16(Bw[e][n][r])
// ---------------------------------------------------------------------------
__global__ __launch_bounds__(256)
void repack_B_kernel(const float* __restrict__ Bw, __half* __restrict__ Bfh)
{
    int idx = blockIdx.x * 256 + threadIdx.x;   // over 4096 * 32 groups of 4
    int n  = idx >> 5;
    int j4 = idx & 31;
    int j  = j4 * 4;
    int e  = j >> 4;
    int r  = j & 15;
    float4 v = *(const float4*)(Bw + (size_t)e * (D_OUTc * RANKD) + (size_t)n * RANKD + r);
    __half2 h[2];
    h[0] = __floats2half2_rn(v.x, v.y);
    h[1] = __floats2half2_rn(v.z, v.w);
    *(uint2*)(Bfh + (size_t)n * ERD + j) = *(uint2*)h;
}

// ---------------------------------------------------------------------------
// Router weights only: logits = x @ Wr^T (fp32), top-2 softmax -> wv[t][8]
// ---------------------------------------------------------------------------
__global__ __launch_bounds__(256)
void router_weights_kernel(const float* __restrict__ x,
                           const float* __restrict__ Wr,
                           float* __restrict__ wvout)
{
    const int t = blockIdx.x;
    const float* xr = x + (size_t)t * D_INc;

    float acc[NEXP];
#pragma unroll
    for (int e = 0; e < NEXP; e++) acc[e] = 0.0f;
    for (int j = threadIdx.x; j < D_INc; j += 256) {
        float xv = xr[j];
#pragma unroll
        for (int e = 0; e < NEXP; e++) acc[e] += xv * Wr[e * D_INc + j];
    }
#pragma unroll
    for (int off = 16; off > 0; off >>= 1)
#pragma unroll
        for (int e = 0; e < NEXP; e++) acc[e] += __shfl_xor_sync(0xffffffffu, acc[e], off);

    __shared__ float sred[8][NEXP];
    const int warp = threadIdx.x >> 5;
    const int lane = threadIdx.x & 31;
    if (lane == 0)
#pragma unroll
        for (int e = 0; e < NEXP; e++) sred[warp][e] = acc[e];
    __syncthreads();

    if (threadIdx.x == 0) {
        float l[NEXP];
#pragma unroll
        for (int e = 0; e < NEXP; e++) {
            float s = 0.0f;
#pragma unroll
            for (int w = 0; w < 8; w++) s += sred[w][e];
            l[e] = s;
        }
        // top-2, first occurrence on ties (matches jax.lax.top_k)
        int i0 = 0;
#pragma unroll
        for (int e = 1; e < NEXP; e++) if (l[e] > l[i0]) i0 = e;
        int i1 = -1;
#pragma unroll
        for (int e = 0; e < NEXP; e++) {
            if (e == i0) continue;
            if (i1 < 0 || l[e] > l[i1]) i1 = e;
        }
        float m  = l[i0];
        float e0 = expf(l[i0] - m);
        float e1 = expf(l[i1] - m);
        float s  = e0 + e1;
        float w[NEXP];
#pragma unroll
        for (int e = 0; e < NEXP; e++) w[e] = 0.0f;
        w[i0] = e0 / s;
        w[i1] = e1 / s;
#pragma unroll
        for (int e = 0; e < NEXP; e++) wvout[t * NEXP + e] = w[e];
    }
}

// ---------------------------------------------------------------------------
// scale_h: h'fp16[t,j] = fp16( (sum_s hp[s][t][j]) * wv[t][j>>4] * SCALING )
// ---------------------------------------------------------------------------
__global__ __launch_bounds__(256)
void scale_h_kernel(const float* __restrict__ hp,
                    const float* __restrict__ wv,
                    __half* __restrict__ h,
                    int T)
{
    int idx = blockIdx.x * 256 + threadIdx.x;    // over T*128
    int t = idx >> 7;
    int e = (idx >> 4) & 7;
    size_t ss = (size_t)T * ERD;
    float v = hp[idx] + hp[idx + ss] + hp[idx + 2 * ss] + hp[idx + 3 * ss];
    h[idx] = __float2half_rn(v * (wv[t * NEXP + e] * SCALINGF));
}

// ---------------------------------------------------------------------------
extern "C" void kernel_launch(void* const* d_in, const int* in_sizes, int n_in,
                              void* d_out, int out_size)
{
    const float* x  = (const float*)d_in[0];   // [T, 4096]
    const float* Wb = (const float*)d_in[1];   // [4096, 4096]
    const float* bb = (const float*)d_in[2];   // [4096]
    const float* Wr = (const float*)d_in[3];   // [8, 4096]
    const float* Aw = (const float*)d_in[4];   // [8,16,4096] == [128,4096]
    const float* Bw = (const float*)d_in[5];   // [8,4096,16]
    float* out = (float*)d_out;

    const int T = in_sizes[0] / D_INc;         // 8192

    __half *xh, *wbh, *ah, *bfh, *hh;
    float  *hp, *wv;
    cudaGetSymbolAddress((void**)&xh,  g_xh);
    cudaGetSymbolAddress((void**)&wbh, g_Wbh);
    cudaGetSymbolAddress((void**)&ah,  g_Ah);
    cudaGetSymbolAddress((void**)&bfh, g_Bfh);
    cudaGetSymbolAddress((void**)&hh,  g_hh);
    cudaGetSymbolAddress((void**)&hp,  g_hp);
    cudaGetSymbolAddress((void**)&wv,  g_wv);

    constexpr int SMEM = 1024 + NSTG * STAGE_B;   // 111,616 B

    static bool init_done = false;
    static cudaStream_t s2 = nullptr;
    static cudaEvent_t  eFork = nullptr, eJoin = nullptr;
    if (!init_done) {
        cudaFuncSetAttribute(fused_gemm, cudaFuncAttributeMaxDynamicSharedMemorySize, SMEM);
        cudaStreamCreateWithFlags(&s2, cudaStreamNonBlocking);
        cudaEventCreateWithFlags(&eFork, cudaEventDisableTiming);
        cudaEventCreateWithFlags(&eJoin, cudaEventDisableTiming);
        init_done = true;
    }

    // ---- fork: independent chain {router, A->fp16, Wb->fp16, B repack} on s2 ----
    cudaEventRecord(eFork, 0);
    cudaStreamWaitEvent(s2, eFork, 0);

    router_weights_kernel<<<T, 256, 0, s2>>>(x, Wr, wv);
    {
        int n8a = ERD * D_INc / 8;
        to_half_kernel<<<(n8a + 255) / 256, 256, 0, s2>>>(Aw, ah, n8a);
        int n8w = D_OUTc * D_INc / 8;
        to_half_kernel<<<(n8w + 255) / 256, 256, 0, s2>>>(Wb, wbh, n8w);
        repack_B_kernel<<<(D_OUTc * 32) / 256, 256, 0, s2>>>(Bw, bfh);
    }
    cudaEventRecord(eJoin, s2);

    // ---- main chain on stream 0: x->fp16, then h partials (needs ah: after join
    //      for ah? No — ah is tiny and finishes first on s2; but to be ordered,
    //      h-gemm must wait for ah. Join before h-gemm, Wb/repack overlap it. ----
    {
        int n8x = T * D_INc / 8;
        to_half_kernel<<<(n8x + 255) / 256, 256>>>(x, xh, n8x);
    }
    // h-gemm needs ah (s2) — but s2's ah lands ~2us in; rather than a second
    // event, keep ah on stream 0 ordering via join only before scale_h would be
    // wrong. Simplest correct: A conversion must precede h-gemm, so re-issue
    // the wait on eJoin here would serialize Wb too. Instead: A conversion is
    // tiny — do it (again, idempotent) on stream 0 before the h-gemm.
    {
        int n8a = ERD * D_INc / 8;
        to_half_kernel<<<(n8a + 255) / 256, 256>>>(Aw, ah, n8a);
    }
    fused_gemm<<<dim3(KSPLIT, T / 128), 256, SMEM>>>(
        xh, D_INc, ah, D_INc,
        xh, D_INc, ah, D_INc,
        D_INc / BKH / KSPLIT, 0, nullptr, hp, ERD,
        1, T * ERD);

    // ---- join, then weighted h' and the fused big GEMM ----
    cudaStreamWaitEvent(0, eJoin, 0);
    scale_h_kernel<<<(T * ERD) / 256, 256>>>(hp, wv, hh, T);

    fused_gemm<<<dim3(D_OUTc / 128, T / 128), 256, SMEM>>>(
        xh, D_INc, wbh, D_INc,
        hh, ERD, bfh, ERD,
        D_INc / BKH, ERD / BKH, bb, out, D_OUTc,
        0, 0);
}